// round 15
// baseline (speedup 1.0000x reference)
#include <cuda_runtime.h>

// ---------------------------------------------------------------------------
// LocalResnetPointnet: PointNet ResNet encoder + scatter_mean to a 128x128 plane
//   B=2, T=65536, hidden=128.
//   Pass 1: fc_pos(3->256) + ResnetBlock0 (K=256)        -> g_h, pool[0]
//   Pass i (1..3): block i with pooled folded into bias   -> g_h, pool[i]
//   Pass 4: block 4 + fused scatter-add + count
//   Final: divide by max(count,1)
// ---------------------------------------------------------------------------

#define BATCH 2
#define TPTS  65536
#define H     128
#define H2    256
#define RESO  128
#define PLANE (RESO*RESO)
#define NPTS  (BATCH*TPTS)       // 131072
#define MT    64                 // points per CTA tile
#define NTILES (NPTS/MT)         // 2048
#define NTHR  256

// -------------------- scratch (device globals; no allocation) --------------
__device__ float    g_h[NPTS * H];             // tiled layout: [tile][k][MT]  (67 MB)
__device__ unsigned g_pool[4][BATCH][H];       // encoded float max
__device__ float    g_c0[BATCH][H];            // b0 + relu(pool) @ w0[128:]
__device__ float    g_cS[BATCH][H];            // b1 + pool @ ws[128:]
__device__ float    g_cnt[BATCH * PLANE];

// monotonic float<->uint encoding for atomicMax
__device__ __forceinline__ unsigned encf(float f) {
    unsigned u = __float_as_uint(f);
    return (u & 0x80000000u) ? ~u : (u | 0x80000000u);
}
__device__ __forceinline__ float decf(unsigned u) {
    return __uint_as_float((u & 0x80000000u) ? (u ^ 0x80000000u) : ~u);
}

// -------------------- GEMM micro-kernel ------------------------------------
// xT: [128][MT] k-major activations in smem, w: [128][128] row-major in smem.
// Each thread: 4 points (pg*4..+3) x 8 cols (cg*8..+7).
template<bool RELU>
__device__ __forceinline__ void gemm_chunk(const float* __restrict__ xT,
                                           const float* __restrict__ w,
                                           int pg, int cg, float acc[4][8])
{
    const float* xp = xT + pg * 4;
    const float* wp = w  + cg * 8;
#pragma unroll 4
    for (int k = 0; k < 128; ++k) {
        float4 a = *reinterpret_cast<const float4*>(xp + k * MT);
        if (RELU) {
            a.x = fmaxf(a.x, 0.f); a.y = fmaxf(a.y, 0.f);
            a.z = fmaxf(a.z, 0.f); a.w = fmaxf(a.w, 0.f);
        }
        float4 u = *reinterpret_cast<const float4*>(wp + k * H);
        float4 v = *reinterpret_cast<const float4*>(wp + k * H + 4);
        float av[4] = {a.x, a.y, a.z, a.w};
        float bv[8] = {u.x, u.y, u.z, u.w, v.x, v.y, v.z, v.w};
#pragma unroll
        for (int i = 0; i < 4; ++i)
#pragma unroll
            for (int j = 0; j < 8; ++j)
                acc[i][j] = fmaf(av[i], bv[j], acc[i][j]);
    }
}

__device__ __forceinline__ void load_w(float* sw, const float* __restrict__ g, int tid) {
    const float4* src = reinterpret_cast<const float4*>(g);
    float4* dst = reinterpret_cast<float4*>(sw);
    for (int i = tid; i < (128 * 128) / 4; i += NTHR) dst[i] = src[i];
}

__device__ __forceinline__ void pool_atomic(const float acc[4][8], int pg, int cg,
                                            int b, int blk)
{
    float m[8];
#pragma unroll
    for (int j = 0; j < 8; ++j) {
        m[j] = fmaxf(fmaxf(acc[0][j], acc[1][j]), fmaxf(acc[2][j], acc[3][j]));
#pragma unroll
        for (int off = 1; off < 16; off <<= 1)
            m[j] = fmaxf(m[j], __shfl_xor_sync(0xffffffffu, m[j], off));
    }
    if (pg == 0) {
#pragma unroll
        for (int j = 0; j < 8; ++j)
            atomicMax(&g_pool[blk][b][cg * 8 + j], encf(m[j]));
    }
}

// -------------------- init: zero out / counts / pools ----------------------
__global__ void k_init(float* __restrict__ out) {
    int stride = gridDim.x * blockDim.x;
    int t0 = blockIdx.x * blockDim.x + threadIdx.x;
    for (int i = t0; i < BATCH * H * PLANE; i += stride) out[i] = 0.f;
    for (int i = t0; i < BATCH * PLANE; i += stride) g_cnt[i] = 0.f;
    unsigned* pool = &g_pool[0][0][0];
    for (int i = t0; i < 4 * BATCH * H; i += stride) pool[i] = 0u;   // < encf(any finite)
}

// -------------------- pass 1: fc_pos + block 0 -----------------------------
// smem: sxT [256][64] (16384) | sw [128][128] (16384) | stT [128][64] (8192)
#define SMEM1_FLOATS (16384 + 16384 + 8192)

__global__ void __launch_bounds__(NTHR) k_pass1(
    const float* __restrict__ p,  const float* __restrict__ fw,
    const float* __restrict__ fb, const float* __restrict__ w0,
    const float* __restrict__ b0, const float* __restrict__ w1,
    const float* __restrict__ b1, const float* __restrict__ ws)
{
    extern __shared__ float sm[];
    float* sxT = sm;               // [256][64]
    float* sw  = sm + 16384;       // [128][128]
    float* stT = sm + 32768;       // [128][64]
    float* sp  = stT;              // reuse as p staging (192 floats)

    const int tid = threadIdx.x, pg = tid & 15, cg = tid >> 4;
    const int tile = blockIdx.x;
    const int g0 = tile * MT;
    const int b  = g0 / TPTS;

    for (int i = tid; i < MT * 3; i += NTHR) sp[i] = p[g0 * 3 + i];
    __syncthreads();

    // x = p @ fc_pos_w + fc_pos_b  -> sxT[c][pt]  (pt fastest -> conflict-free STS)
    for (int i = tid; i < MT * H2; i += NTHR) {
        int pt = i & (MT - 1);
        int c  = i / MT;
        float v = fb[c];
        v = fmaf(sp[pt * 3 + 0], fw[c],          v);
        v = fmaf(sp[pt * 3 + 1], fw[H2 + c],     v);
        v = fmaf(sp[pt * 3 + 2], fw[2 * H2 + c], v);
        sxT[c * MT + pt] = v;
    }
    __syncthreads();   // sp / stT free after this

    float acc[4][8];
    // ---- stage 1: t = relu(x) @ w0[0] + b0[0]   (K = 256, two chunks)
#pragma unroll
    for (int j = 0; j < 8; ++j) {
        float bb = b0[cg * 8 + j];
#pragma unroll
        for (int i = 0; i < 4; ++i) acc[i][j] = bb;
    }
    load_w(sw, w0, tid);
    __syncthreads();
    gemm_chunk<true>(sxT, sw, pg, cg, acc);
    __syncthreads();
    load_w(sw, w0 + 128 * H, tid);
    __syncthreads();
    gemm_chunk<true>(sxT + 128 * MT, sw, pg, cg, acc);

    // write t transposed
#pragma unroll
    for (int j = 0; j < 8; ++j)
#pragma unroll
        for (int i = 0; i < 4; ++i)
            stT[(cg * 8 + j) * MT + pg * 4 + i] = acc[i][j];
    __syncthreads();

    // ---- stage 2+3: h = (relu(t) @ w1[0] + b1[0]) + x @ ws[0]
#pragma unroll
    for (int j = 0; j < 8; ++j) {
        float bb = b1[cg * 8 + j];
#pragma unroll
        for (int i = 0; i < 4; ++i) acc[i][j] = bb;
    }
    load_w(sw, w1, tid);
    __syncthreads();
    gemm_chunk<true>(stT, sw, pg, cg, acc);
    __syncthreads();
    load_w(sw, ws, tid);
    __syncthreads();
    gemm_chunk<false>(sxT, sw, pg, cg, acc);
    __syncthreads();
    load_w(sw, ws + 128 * H, tid);
    __syncthreads();
    gemm_chunk<false>(sxT + 128 * MT, sw, pg, cg, acc);

    pool_atomic(acc, pg, cg, b, 0);

    // stage out (transposed, k-major) and store tile
    __syncthreads();
#pragma unroll
    for (int j = 0; j < 8; ++j)
#pragma unroll
        for (int i = 0; i < 4; ++i)
            sw[(cg * 8 + j) * MT + pg * 4 + i] = acc[i][j];
    __syncthreads();
    float4* dst = reinterpret_cast<float4*>(g_h + tile * MT * H);
    const float4* s4 = reinterpret_cast<const float4*>(sw);
    for (int i = tid; i < (MT * H) / 4; i += NTHR) dst[i] = s4[i];
}

// -------------------- per-block bias fold (tiny) ---------------------------
__global__ void k_bias(int blk, const float* __restrict__ w0, const float* __restrict__ b0,
                       const float* __restrict__ w1, const float* __restrict__ b1,
                       const float* __restrict__ ws)
{
    (void)w1;
    int t = threadIdx.x;            // 256 threads: (b, col)
    int b = t >> 7, col = t & 127;
    const float* w0b = w0 + blk * H2 * H + 128 * H;   // rows 128..255
    const float* wsb = ws + blk * H2 * H + 128 * H;
    float c0 = b0[blk * H + col];
    float cS = b1[blk * H + col];
    for (int c = 0; c < H; ++c) {
        float pl = decf(g_pool[blk - 1][b][c]);
        c0 = fmaf(fmaxf(pl, 0.f), w0b[c * H + col], c0);
        cS = fmaf(pl,             wsb[c * H + col], cS);
    }
    g_c0[b][col] = c0;
    g_cS[b][col] = cS;
}

// -------------------- blocks 1..4 (blk==4 fuses scatter) -------------------
// smem: sxT [128][64] (8192) | sw (16384) | stT (8192)
#define SMEM2_FLOATS (8192 + 16384 + 8192)

__global__ void __launch_bounds__(NTHR) k_block(
    int blk, const float* __restrict__ w0, const float* __restrict__ w1,
    const float* __restrict__ ws, const float* __restrict__ p,
    float* __restrict__ out)
{
    extern __shared__ float sm[];
    float* sxT = sm;             // [128][64]
    float* sw  = sm + 8192;      // [128][128]
    float* stT = sm + 24576;     // [128][64]

    const int tid = threadIdx.x, pg = tid & 15, cg = tid >> 4;
    const int tile = blockIdx.x;
    const int g0 = tile * MT;
    const int b  = g0 / TPTS;

    {   // load h tile (already k-major on disk)
        const float4* src = reinterpret_cast<const float4*>(g_h + tile * MT * H);
        float4* d4 = reinterpret_cast<float4*>(sxT);
        for (int i = tid; i < (MT * H) / 4; i += NTHR) d4[i] = src[i];
    }
    __syncthreads();

    float acc[4][8];
    // ---- t = relu(h) @ w0a + c0
#pragma unroll
    for (int j = 0; j < 8; ++j) {
        float bb = g_c0[b][cg * 8 + j];
#pragma unroll
        for (int i = 0; i < 4; ++i) acc[i][j] = bb;
    }
    load_w(sw, w0 + blk * H2 * H, tid);      // rows 0..127 only
    __syncthreads();
    gemm_chunk<true>(sxT, sw, pg, cg, acc);
    __syncthreads();
#pragma unroll
    for (int j = 0; j < 8; ++j)
#pragma unroll
        for (int i = 0; i < 4; ++i)
            stT[(cg * 8 + j) * MT + pg * 4 + i] = acc[i][j];
    __syncthreads();

    // ---- h_out = cS' + relu(t) @ w1 + h @ wsa
#pragma unroll
    for (int j = 0; j < 8; ++j) {
        float bb = g_cS[b][cg * 8 + j];
#pragma unroll
        for (int i = 0; i < 4; ++i) acc[i][j] = bb;
    }
    load_w(sw, w1 + blk * H * H, tid);
    __syncthreads();
    gemm_chunk<true>(stT, sw, pg, cg, acc);
    __syncthreads();
    load_w(sw, ws + blk * H2 * H, tid);      // rows 0..127 only
    __syncthreads();
    gemm_chunk<false>(sxT, sw, pg, cg, acc);

    if (blk < 4) {
        pool_atomic(acc, pg, cg, b, blk);
        __syncthreads();
#pragma unroll
        for (int j = 0; j < 8; ++j)
#pragma unroll
            for (int i = 0; i < 4; ++i)
                sw[(cg * 8 + j) * MT + pg * 4 + i] = acc[i][j];
        __syncthreads();
        float4* dst = reinterpret_cast<float4*>(g_h + tile * MT * H);
        const float4* s4 = reinterpret_cast<const float4*>(sw);
        for (int i = tid; i < (MT * H) / 4; i += NTHR) dst[i] = s4[i];
    } else {
        // fused scatter-add (acc = final per-point feature c)
#pragma unroll
        for (int i4 = 0; i4 < 4; ++i4) {
            int pt = pg * 4 + i4;
            int g  = g0 + pt;
            float px = p[g * 3 + 0];
            float pz = p[g * 3 + 2];
            // matches reference fp32 math exactly (IEEE division, truncation)
            float x0 = __fdiv_rn(px, 1.101f) + 0.5f;
            float x1 = __fdiv_rn(pz, 1.101f) + 0.5f;
            x0 = fminf(fmaxf(x0, 0.f), 0.999999f);
            x1 = fminf(fmaxf(x1, 0.f), 0.999999f);
            int xi0 = (int)(x0 * 128.0f);
            int xi1 = (int)(x1 * 128.0f);
            int idx = xi0 + RESO * xi1;
            float* ob = out + (b * H) * PLANE + idx;
#pragma unroll
            for (int j = 0; j < 8; ++j)
                atomicAdd(ob + (cg * 8 + j) * PLANE, acc[i4][j]);
            if (cg == 0)
                atomicAdd(&g_cnt[b * PLANE + idx], 1.0f);
        }
    }
}

// -------------------- normalize: mean = sum / max(count,1) -----------------
__global__ void k_norm(float* __restrict__ out) {
    int n = BATCH * H * PLANE;
    int stride = gridDim.x * blockDim.x;
    for (int e = blockIdx.x * blockDim.x + threadIdx.x; e < n; e += stride) {
        int b   = e / (H * PLANE);
        int idx = e % PLANE;
        float c = g_cnt[b * PLANE + idx];
        out[e] = out[e] / fmaxf(c, 1.0f);
    }
}

// -------------------- launch -----------------------------------------------
extern "C" void kernel_launch(void* const* d_in, const int* in_sizes, int n_in,
                              void* d_out, int out_size)
{
    (void)in_sizes; (void)n_in; (void)out_size;
    const float* p  = (const float*)d_in[0];
    const float* fw = (const float*)d_in[1];
    const float* fb = (const float*)d_in[2];
    const float* w0 = (const float*)d_in[3];
    const float* b0 = (const float*)d_in[4];
    const float* w1 = (const float*)d_in[5];
    const float* b1 = (const float*)d_in[6];
    const float* ws = (const float*)d_in[7];
    float* out = (float*)d_out;

    const int smem1 = SMEM1_FLOATS * (int)sizeof(float);   // 163840 B
    const int smem2 = SMEM2_FLOATS * (int)sizeof(float);   // 131072 B
    cudaFuncSetAttribute(k_pass1, cudaFuncAttributeMaxDynamicSharedMemorySize, smem1);
    cudaFuncSetAttribute(k_block, cudaFuncAttributeMaxDynamicSharedMemorySize, smem2);

    k_init<<<512, 256>>>(out);
    k_pass1<<<NTILES, NTHR, smem1>>>(p, fw, fb, w0, b0, w1, b1, ws);
    for (int blk = 1; blk <= 4; ++blk) {
        k_bias<<<1, 256>>>(blk, w0, b0, w1, b1, ws);
        k_block<<<NTILES, NTHR, smem2>>>(blk, w0, w1, ws, p, out);
    }
    k_norm<<<2048, 512>>>(out);
}

// round 16
// speedup vs baseline: 1.0038x; 1.0038x over previous
#include <cuda_runtime.h>

// ---------------------------------------------------------------------------
// LocalResnetPointnet: PointNet ResNet encoder + scatter_mean to a 128x128 plane
//   B=2, T=65536, hidden=128.
//   Pass 1: fc_pos(3->256) + ResnetBlock0 (K=256)        -> g_h, pool[0]
//   Pass i (1..3): block i with pooled folded into bias   -> g_h, pool[i]
//   Pass 4: block 4 + fused scatter-add + count
//   Final: divide by max(count,1)
// ---------------------------------------------------------------------------

#define BATCH 2
#define TPTS  65536
#define H     128
#define H2    256
#define RESO  128
#define PLANE (RESO*RESO)
#define NPTS  (BATCH*TPTS)       // 131072
#define MT    64                 // points per CTA tile
#define NTILES (NPTS/MT)         // 2048
#define NTHR  256

// -------------------- scratch (device globals; no allocation) --------------
__device__ float    g_h[NPTS * H];             // tiled layout: [tile][k][MT]  (67 MB)
__device__ unsigned g_pool[4][BATCH][H];       // encoded float max
__device__ float    g_c0[BATCH][H];            // b0 + relu(pool) @ w0[128:]
__device__ float    g_cS[BATCH][H];            // b1 + pool @ ws[128:]
__device__ float    g_cnt[BATCH * PLANE];

// monotonic float<->uint encoding for atomicMax
__device__ __forceinline__ unsigned encf(float f) {
    unsigned u = __float_as_uint(f);
    return (u & 0x80000000u) ? ~u : (u | 0x80000000u);
}
__device__ __forceinline__ float decf(unsigned u) {
    return __uint_as_float((u & 0x80000000u) ? (u ^ 0x80000000u) : ~u);
}

// -------------------- GEMM micro-kernel ------------------------------------
// xT: [128][MT] k-major activations in smem, w: [128][128] row-major in smem.
// Each thread: 4 points (pg*4..+3) x 8 cols (cg*8..+7).
template<bool RELU>
__device__ __forceinline__ void gemm_chunk(const float* __restrict__ xT,
                                           const float* __restrict__ w,
                                           int pg, int cg, float acc[4][8])
{
    const float* xp = xT + pg * 4;
    const float* wp = w  + cg * 8;
#pragma unroll 4
    for (int k = 0; k < 128; ++k) {
        float4 a = *reinterpret_cast<const float4*>(xp + k * MT);
        if (RELU) {
            a.x = fmaxf(a.x, 0.f); a.y = fmaxf(a.y, 0.f);
            a.z = fmaxf(a.z, 0.f); a.w = fmaxf(a.w, 0.f);
        }
        float4 u = *reinterpret_cast<const float4*>(wp + k * H);
        float4 v = *reinterpret_cast<const float4*>(wp + k * H + 4);
        float av[4] = {a.x, a.y, a.z, a.w};
        float bv[8] = {u.x, u.y, u.z, u.w, v.x, v.y, v.z, v.w};
#pragma unroll
        for (int i = 0; i < 4; ++i)
#pragma unroll
            for (int j = 0; j < 8; ++j)
                acc[i][j] = fmaf(av[i], bv[j], acc[i][j]);
    }
}

__device__ __forceinline__ void load_w(float* sw, const float* __restrict__ g, int tid) {
    const float4* src = reinterpret_cast<const float4*>(g);
    float4* dst = reinterpret_cast<float4*>(sw);
    for (int i = tid; i < (128 * 128) / 4; i += NTHR) dst[i] = src[i];
}

__device__ __forceinline__ void pool_atomic(const float acc[4][8], int pg, int cg,
                                            int b, int blk)
{
    float m[8];
#pragma unroll
    for (int j = 0; j < 8; ++j) {
        m[j] = fmaxf(fmaxf(acc[0][j], acc[1][j]), fmaxf(acc[2][j], acc[3][j]));
#pragma unroll
        for (int off = 1; off < 16; off <<= 1)
            m[j] = fmaxf(m[j], __shfl_xor_sync(0xffffffffu, m[j], off));
    }
    if (pg == 0) {
#pragma unroll
        for (int j = 0; j < 8; ++j)
            atomicMax(&g_pool[blk][b][cg * 8 + j], encf(m[j]));
    }
}

// -------------------- init: zero out / counts / pools ----------------------
__global__ void k_init(float* __restrict__ out) {
    int stride = gridDim.x * blockDim.x;
    int t0 = blockIdx.x * blockDim.x + threadIdx.x;
    for (int i = t0; i < BATCH * H * PLANE; i += stride) out[i] = 0.f;
    for (int i = t0; i < BATCH * PLANE; i += stride) g_cnt[i] = 0.f;
    unsigned* pool = &g_pool[0][0][0];
    for (int i = t0; i < 4 * BATCH * H; i += stride) pool[i] = 0u;   // < encf(any finite)
}

// -------------------- pass 1: fc_pos + block 0 -----------------------------
// smem: sxT [256][64] (16384) | sw [128][128] (16384) | stT [128][64] (8192)
#define SMEM1_FLOATS (16384 + 16384 + 8192)

__global__ void __launch_bounds__(NTHR) k_pass1(
    const float* __restrict__ p,  const float* __restrict__ fw,
    const float* __restrict__ fb, const float* __restrict__ w0,
    const float* __restrict__ b0, const float* __restrict__ w1,
    const float* __restrict__ b1, const float* __restrict__ ws)
{
    extern __shared__ float sm[];
    float* sxT = sm;               // [256][64]
    float* sw  = sm + 16384;       // [128][128]
    float* stT = sm + 32768;       // [128][64]
    float* sp  = stT;              // reuse as p staging (192 floats)

    const int tid = threadIdx.x, pg = tid & 15, cg = tid >> 4;
    const int tile = blockIdx.x;
    const int g0 = tile * MT;
    const int b  = g0 / TPTS;

    for (int i = tid; i < MT * 3; i += NTHR) sp[i] = p[g0 * 3 + i];
    __syncthreads();

    // x = p @ fc_pos_w + fc_pos_b  -> sxT[c][pt]  (pt fastest -> conflict-free STS)
    for (int i = tid; i < MT * H2; i += NTHR) {
        int pt = i & (MT - 1);
        int c  = i / MT;
        float v = fb[c];
        v = fmaf(sp[pt * 3 + 0], fw[c],          v);
        v = fmaf(sp[pt * 3 + 1], fw[H2 + c],     v);
        v = fmaf(sp[pt * 3 + 2], fw[2 * H2 + c], v);
        sxT[c * MT + pt] = v;
    }
    __syncthreads();   // sp / stT free after this

    float acc[4][8];
    // ---- stage 1: t = relu(x) @ w0[0] + b0[0]   (K = 256, two chunks)
#pragma unroll
    for (int j = 0; j < 8; ++j) {
        float bb = b0[cg * 8 + j];
#pragma unroll
        for (int i = 0; i < 4; ++i) acc[i][j] = bb;
    }
    load_w(sw, w0, tid);
    __syncthreads();
    gemm_chunk<true>(sxT, sw, pg, cg, acc);
    __syncthreads();
    load_w(sw, w0 + 128 * H, tid);
    __syncthreads();
    gemm_chunk<true>(sxT + 128 * MT, sw, pg, cg, acc);

    // write t transposed
#pragma unroll
    for (int j = 0; j < 8; ++j)
#pragma unroll
        for (int i = 0; i < 4; ++i)
            stT[(cg * 8 + j) * MT + pg * 4 + i] = acc[i][j];
    __syncthreads();

    // ---- stage 2+3: h = (relu(t) @ w1[0] + b1[0]) + x @ ws[0]
#pragma unroll
    for (int j = 0; j < 8; ++j) {
        float bb = b1[cg * 8 + j];
#pragma unroll
        for (int i = 0; i < 4; ++i) acc[i][j] = bb;
    }
    load_w(sw, w1, tid);
    __syncthreads();
    gemm_chunk<true>(stT, sw, pg, cg, acc);
    __syncthreads();
    load_w(sw, ws, tid);
    __syncthreads();
    gemm_chunk<false>(sxT, sw, pg, cg, acc);
    __syncthreads();
    load_w(sw, ws + 128 * H, tid);
    __syncthreads();
    gemm_chunk<false>(sxT + 128 * MT, sw, pg, cg, acc);

    pool_atomic(acc, pg, cg, b, 0);

    // stage out (transposed, k-major) and store tile
    __syncthreads();
#pragma unroll
    for (int j = 0; j < 8; ++j)
#pragma unroll
        for (int i = 0; i < 4; ++i)
            sw[(cg * 8 + j) * MT + pg * 4 + i] = acc[i][j];
    __syncthreads();
    float4* dst = reinterpret_cast<float4*>(g_h + tile * MT * H);
    const float4* s4 = reinterpret_cast<const float4*>(sw);
    for (int i = tid; i < (MT * H) / 4; i += NTHR) dst[i] = s4[i];
}

// -------------------- per-block bias fold (tiny) ---------------------------
__global__ void k_bias(int blk, const float* __restrict__ w0, const float* __restrict__ b0,
                       const float* __restrict__ w1, const float* __restrict__ b1,
                       const float* __restrict__ ws)
{
    (void)w1;
    int t = threadIdx.x;            // 256 threads: (b, col)
    int b = t >> 7, col = t & 127;
    const float* w0b = w0 + blk * H2 * H + 128 * H;   // rows 128..255
    const float* wsb = ws + blk * H2 * H + 128 * H;
    float c0 = b0[blk * H + col];
    float cS = b1[blk * H + col];
    for (int c = 0; c < H; ++c) {
        float pl = decf(g_pool[blk - 1][b][c]);
        c0 = fmaf(fmaxf(pl, 0.f), w0b[c * H + col], c0);
        cS = fmaf(pl,             wsb[c * H + col], cS);
    }
    g_c0[b][col] = c0;
    g_cS[b][col] = cS;
}

// -------------------- blocks 1..4 (blk==4 fuses scatter) -------------------
// smem: sxT [128][64] (8192) | sw (16384) | stT (8192)
#define SMEM2_FLOATS (8192 + 16384 + 8192)

__global__ void __launch_bounds__(NTHR) k_block(
    int blk, const float* __restrict__ w0, const float* __restrict__ w1,
    const float* __restrict__ ws, const float* __restrict__ p,
    float* __restrict__ out)
{
    extern __shared__ float sm[];
    float* sxT = sm;             // [128][64]
    float* sw  = sm + 8192;      // [128][128]
    float* stT = sm + 24576;     // [128][64]

    const int tid = threadIdx.x, pg = tid & 15, cg = tid >> 4;
    const int tile = blockIdx.x;
    const int g0 = tile * MT;
    const int b  = g0 / TPTS;

    {   // load h tile (already k-major on disk)
        const float4* src = reinterpret_cast<const float4*>(g_h + tile * MT * H);
        float4* d4 = reinterpret_cast<float4*>(sxT);
        for (int i = tid; i < (MT * H) / 4; i += NTHR) d4[i] = src[i];
    }
    __syncthreads();

    float acc[4][8];
    // ---- t = relu(h) @ w0a + c0
#pragma unroll
    for (int j = 0; j < 8; ++j) {
        float bb = g_c0[b][cg * 8 + j];
#pragma unroll
        for (int i = 0; i < 4; ++i) acc[i][j] = bb;
    }
    load_w(sw, w0 + blk * H2 * H, tid);      // rows 0..127 only
    __syncthreads();
    gemm_chunk<true>(sxT, sw, pg, cg, acc);
    __syncthreads();
#pragma unroll
    for (int j = 0; j < 8; ++j)
#pragma unroll
        for (int i = 0; i < 4; ++i)
            stT[(cg * 8 + j) * MT + pg * 4 + i] = acc[i][j];
    __syncthreads();

    // ---- h_out = cS' + relu(t) @ w1 + h @ wsa
#pragma unroll
    for (int j = 0; j < 8; ++j) {
        float bb = g_cS[b][cg * 8 + j];
#pragma unroll
        for (int i = 0; i < 4; ++i) acc[i][j] = bb;
    }
    load_w(sw, w1 + blk * H * H, tid);
    __syncthreads();
    gemm_chunk<true>(stT, sw, pg, cg, acc);
    __syncthreads();
    load_w(sw, ws + blk * H2 * H, tid);      // rows 0..127 only
    __syncthreads();
    gemm_chunk<false>(sxT, sw, pg, cg, acc);

    if (blk < 4) {
        pool_atomic(acc, pg, cg, b, blk);
        __syncthreads();
#pragma unroll
        for (int j = 0; j < 8; ++j)
#pragma unroll
            for (int i = 0; i < 4; ++i)
                sw[(cg * 8 + j) * MT + pg * 4 + i] = acc[i][j];
        __syncthreads();
        float4* dst = reinterpret_cast<float4*>(g_h + tile * MT * H);
        const float4* s4 = reinterpret_cast<const float4*>(sw);
        for (int i = tid; i < (MT * H) / 4; i += NTHR) dst[i] = s4[i];
    } else {
        // fused scatter-add (acc = final per-point feature c)
#pragma unroll
        for (int i4 = 0; i4 < 4; ++i4) {
            int pt = pg * 4 + i4;
            int g  = g0 + pt;
            float px = p[g * 3 + 0];
            float pz = p[g * 3 + 2];
            // matches reference fp32 math exactly (IEEE division, truncation)
            float x0 = __fdiv_rn(px, 1.101f) + 0.5f;
            float x1 = __fdiv_rn(pz, 1.101f) + 0.5f;
            x0 = fminf(fmaxf(x0, 0.f), 0.999999f);
            x1 = fminf(fmaxf(x1, 0.f), 0.999999f);
            int xi0 = (int)(x0 * 128.0f);
            int xi1 = (int)(x1 * 128.0f);
            int idx = xi0 + RESO * xi1;
            float* ob = out + (b * H) * PLANE + idx;
#pragma unroll
            for (int j = 0; j < 8; ++j)
                atomicAdd(ob + (cg * 8 + j) * PLANE, acc[i4][j]);
            if (cg == 0)
                atomicAdd(&g_cnt[b * PLANE + idx], 1.0f);
        }
    }
}

// -------------------- normalize: mean = sum / max(count,1) -----------------
__global__ void k_norm(float* __restrict__ out) {
    int n = BATCH * H * PLANE;
    int stride = gridDim.x * blockDim.x;
    for (int e = blockIdx.x * blockDim.x + threadIdx.x; e < n; e += stride) {
        int b   = e / (H * PLANE);
        int idx = e % PLANE;
        float c = g_cnt[b * PLANE + idx];
        out[e] = out[e] / fmaxf(c, 1.0f);
    }
}

// -------------------- launch -----------------------------------------------
extern "C" void kernel_launch(void* const* d_in, const int* in_sizes, int n_in,
                              void* d_out, int out_size)
{
    (void)in_sizes; (void)n_in; (void)out_size;
    const float* p  = (const float*)d_in[0];
    const float* fw = (const float*)d_in[1];
    const float* fb = (const float*)d_in[2];
    const float* w0 = (const float*)d_in[3];
    const float* b0 = (const float*)d_in[4];
    const float* w1 = (const float*)d_in[5];
    const float* b1 = (const float*)d_in[6];
    const float* ws = (const float*)d_in[7];
    float* out = (float*)d_out;

    const int smem1 = SMEM1_FLOATS * (int)sizeof(float);   // 163840 B
    const int smem2 = SMEM2_FLOATS * (int)sizeof(float);   // 131072 B
    cudaFuncSetAttribute(k_pass1, cudaFuncAttributeMaxDynamicSharedMemorySize, smem1);
    cudaFuncSetAttribute(k_block, cudaFuncAttributeMaxDynamicSharedMemorySize, smem2);

    k_init<<<512, 256>>>(out);
    k_pass1<<<NTILES, NTHR, smem1>>>(p, fw, fb, w0, b0, w1, b1, ws);
    for (int blk = 1; blk <= 4; ++blk) {
        k_bias<<<1, 256>>>(blk, w0, b0, w1, b1, ws);
        k_block<<<NTILES, NTHR, smem2>>>(blk, w0, w1, ws, p, out);
    }
    k_norm<<<2048, 512>>>(out);
}